// round 4
// baseline (speedup 1.0000x reference)
#include <cuda_runtime.h>
#include <math.h>

// Problem constants (B=1, C_IN=3, H=W=96, FEAT=64, GDIM=8, BLOCK=16)
#define Hh   96
#define Ww   96
#define HW   (96 * 96)
#define GD   8
#define FEAT 64
#define CIN  3
#define TWt  6
#define THt  6

#define NB   144     // blocks  (144 <= 148 SMs -> all co-resident, barrier is safe)
#define NT   64      // threads (144 * 64 == 9216 == HW, one gaussian/pixel per thread)

struct __align__(16) GParam {
    float cx, cy, ca, cb, cc;
    float r0, r1, r2;
    int tminx, tmaxx, tminy, tmaxy;
};

__device__ GParam g_gauss[HW];       // 442 KB scratch (device global: no allocations)
__device__ int    g_arrive = 0;      // grid barrier counters (self-resetting each launch)
__device__ int    g_depart = 0;

// ---------------------------------------------------------------------------
// Fused kernel:
//   phase A: per-thread gaussian parameter computation (collapsed conv+head)
//   device-wide spin barrier (all NB blocks resident in wave 1)
//   phase B: per-pixel gather over the provably-sufficient 7x7 window with
//            sigma-based early rejection (exactly equivalent to alpha>=1/255)
// ---------------------------------------------------------------------------
__global__ __launch_bounds__(NT)
void fused_gaussian_kernel(const float* __restrict__ inp,
                           const float* __restrict__ w_enc,
                           const float* __restrict__ b_enc,
                           const float* __restrict__ w_head,
                           const float* __restrict__ b_head,
                           float* __restrict__ out)
{
    __shared__ float sw[GD * 27];   // w_eff[o][ci*9+ky*3+kx]
    __shared__ float sb[GD];        // b_eff[o]

    const int tid = threadIdx.x;
    const int bid = blockIdx.x;

    // ---- collapsed conv+head weights (redundant per block, trivial cost) ----
    for (int t = tid; t < GD * 27 + GD; t += NT) {
        if (t < GD * 27) {
            const int o = t / 27, k = t % 27;
            float acc = 0.f;
            #pragma unroll 8
            for (int c = 0; c < FEAT; ++c)
                acc += __ldg(&w_head[o * FEAT + c]) * __ldg(&w_enc[c * 27 + k]);
            sw[t] = acc;
        } else {
            const int o = t - GD * 27;
            float acc = __ldg(&b_head[o]);
            #pragma unroll 8
            for (int c = 0; c < FEAT; ++c)
                acc += __ldg(&w_head[o * FEAT + c]) * __ldg(&b_enc[c]);
            sb[o] = acc;
        }
    }
    __syncthreads();

    const int p = bid * NT + tid;          // in [0, HW) exactly
    const int w = p % Ww;
    const int h = p / Ww;

    // ---- phase A: gaussian parameters --------------------------------------
    {
        float pred[GD];
        #pragma unroll
        for (int o = 0; o < GD; ++o) pred[o] = sb[o];

        // Effective 3x3x3 conv, SAME zero padding.
        #pragma unroll
        for (int ci = 0; ci < CIN; ++ci) {
            #pragma unroll
            for (int ky = 0; ky < 3; ++ky) {
                const int y = h + ky - 1;
                #pragma unroll
                for (int kx = 0; kx < 3; ++kx) {
                    const int x = w + kx - 1;
                    float v = 0.f;
                    if (y >= 0 && y < Hh && x >= 0 && x < Ww)
                        v = __ldg(&inp[ci * HW + y * Ww + x]);
                    const int k = ci * 9 + ky * 3 + kx;
                    #pragma unroll
                    for (int o = 0; o < GD; ++o)
                        pred[o] += v * sw[o * 27 + k];
                }
            }
        }

        const float theta = (1.f / (1.f + expf(-pred[3]))) * 6.283185307179586f;
        const float s0 = (1.f / (1.f + expf(-pred[4]))) * 0.5f + 1e-6f;
        const float s1 = (1.f / (1.f + expf(-pred[5]))) * 0.5f + 1e-6f;
        const float off0 = tanhf(pred[6]);
        const float off1 = tanhf(pred[7]);

        const float c = cosf(theta), s = sinf(theta);
        const float v0 = s0 * s0, v1 = s1 * s1;
        const float S00 = c * c * v0 + s * s * v1;
        const float S01 = c * s * (v0 - v1);
        const float S11 = s * s * v0 + c * c * v1;
        const float det = S00 * S11 - S01 * S01;
        const float inv_det = 1.f / det;
        const float bmid = 0.5f * (S00 + S11);
        const float lam1 = bmid + sqrtf(fmaxf(0.1f, bmid * bmid - det));
        const float radius = ceilf(3.0f * sqrtf(lam1));

        const float coord0 = 2.0f * (float)w / (float)Ww - 1.0f;
        const float coord1 = 2.0f * (float)h / (float)Hh - 1.0f;
        const float x_ndc = coord0 + 2.0f * off0 / (float)Ww - 1.0f / (float)Ww;
        const float y_ndc = coord1 + 2.0f * off1 / (float)Hh - 1.0f / (float)Hh;
        const float cx = 0.5f * (float)Ww * (x_ndc + 1.0f) - 0.5f;
        const float cy = 0.5f * (float)Hh * (y_ndc + 1.0f) - 0.5f;

        int tmin_x = min(max((int)((cx - radius) / 16.0f), 0), TWt);
        int tmax_x = min(max((int)((cx + radius) / 16.0f) + 1, 0), TWt);
        int tmin_y = min(max((int)((cy - radius) / 16.0f), 0), THt);
        int tmax_y = min(max((int)((cy + radius) / 16.0f) + 1, 0), THt);
        if (!(radius > 0.0f)) { tmax_x = tmin_x; tmax_y = tmin_y; }

        GParam g;
        g.cx = cx; g.cy = cy;
        g.ca =  S11 * inv_det;
        g.cb = -S01 * inv_det;
        g.cc =  S00 * inv_det;
        g.r0 = pred[0]; g.r1 = pred[1]; g.r2 = pred[2];
        g.tminx = tmin_x; g.tmaxx = tmax_x; g.tminy = tmin_y; g.tmaxy = tmax_y;
        g_gauss[p] = g;
    }

    // ---- device-wide barrier ----------------------------------------------
    __threadfence();                       // publish g_gauss to GPU scope
    __syncthreads();                       // whole block's writes done
    if (tid == 0) {
        atomicAdd(&g_arrive, 1);
        while (*(volatile int*)&g_arrive < NB) { }
        __threadfence();
        atomicAdd(&g_depart, 1);           // mark "I will never read g_arrive again"
    }
    __syncthreads();                       // block released; g_gauss fully visible

    // ---- phase B: rasterize pixel p ---------------------------------------
    {
        const int px = w;
        const int py = h;
        const int tx = px >> 4;
        const int ty = py >> 4;
        const float fpx = (float)px;
        const float fpy = (float)py;

        float a0 = 0.f, a1 = 0.f, a2 = 0.f;

        // alpha >= 1/255  <=>  sigma <= ln(255) = 5.54126.
        // lam_max(Sigma) <= 0.25 and |tanh offset| < 1 bound the footprint to
        // the 7x7 gaussian window [p-2, p+4]; the sigma gate below makes the
        // exp-path decision exactly equivalent to the reference's alpha test.
        #pragma unroll
        for (int dgh = 0; dgh < 7; ++dgh) {
            const int gh = py - 2 + dgh;
            if (gh < 0 || gh >= Hh) continue;
            const GParam* __restrict__ row = &g_gauss[gh * Ww];
            #pragma unroll
            for (int dgw = 0; dgw < 7; ++dgw) {
                const int gw = px - 2 + dgw;
                if (gw < 0 || gw >= Ww) continue;
                const GParam g = row[gw];
                const float dx = g.cx - fpx;
                const float dy = g.cy - fpy;
                const float sigma = 0.5f * (g.ca * dx * dx + g.cc * dy * dy) + g.cb * dx * dy;
                if (!(sigma >= 0.f) || sigma > 5.5421f) continue;   // reject w/o exp
                const float alpha = fminf(0.999f, expf(-sigma));
                if (alpha < (1.0f / 255.0f)) continue;
                if (tx < g.tminx || tx >= g.tmaxx || ty < g.tminy || ty >= g.tmaxy) continue;
                a0 += alpha * g.r0;
                a1 += alpha * g.r1;
                a2 += alpha * g.r2;
            }
        }

        out[0 * HW + p] = fminf(fmaxf(a0, 0.f), 1.f);
        out[1 * HW + p] = fminf(fmaxf(a1, 0.f), 1.f);
        out[2 * HW + p] = fminf(fmaxf(a2, 0.f), 1.f);
    }

    // ---- reset barrier counters for the next graph replay ------------------
    if (bid == 0 && tid == 0) {
        while (*(volatile int*)&g_depart < NB) { }  // nobody will touch g_arrive again
        atomicExch(&g_arrive, 0);
        atomicExch(&g_depart, 0);
    }
}

// ---------------------------------------------------------------------------
extern "C" void kernel_launch(void* const* d_in, const int* in_sizes, int n_in,
                              void* d_out, int out_size)
{
    const float* inp    = (const float*)d_in[0];
    const float* w_enc  = (const float*)d_in[1];
    const float* b_enc  = (const float*)d_in[2];
    const float* w_head = (const float*)d_in[3];
    const float* b_head = (const float*)d_in[4];
    float* out = (float*)d_out;

    fused_gaussian_kernel<<<NB, NT>>>(inp, w_enc, b_enc, w_head, b_head, out);
}

// round 5
// speedup vs baseline: 1.5115x; 1.5115x over previous
#include <cuda_runtime.h>
#include <math.h>

// Problem constants (B=1, C_IN=3, H=W=96, FEAT=64, GDIM=8, BLOCK=16)
#define Hh   96
#define Ww   96
#define HW   (96 * 96)
#define GD   8
#define FEAT 64
#define CIN  3
#define TWt  6
#define THt  6

#define LN255 5.5412635f   // ln(255); alpha >= 1/255  <=>  sigma <= ln(255)

struct __align__(16) GParam {
    float cx, cy, ca, cb, cc;
    float r0, r1, r2;
    int tminx, tmaxx, tminy, tmaxy;
};

__device__ GParam g_gauss[HW];   // 442 KB scratch (device global: no allocations)

// ---------------------------------------------------------------------------
// Kernel 1: per-gaussian parameters. 144 blocks x 64 threads = 9216 gaussians,
// full-chip coverage. Each block builds the collapsed conv+head weights in
// shared memory (trivial, redundant), then each thread computes one gaussian.
// ---------------------------------------------------------------------------
__global__ __launch_bounds__(64)
void gauss_params_kernel(const float* __restrict__ inp,
                         const float* __restrict__ w_enc,
                         const float* __restrict__ b_enc,
                         const float* __restrict__ w_head,
                         const float* __restrict__ b_head)
{
    __shared__ float sw[GD * 27];
    __shared__ float sb[GD];

    const int tid = threadIdx.x;

    for (int t = tid; t < GD * 27 + GD; t += 64) {
        if (t < GD * 27) {
            const int o = t / 27, k = t % 27;
            float acc = 0.f;
            #pragma unroll 8
            for (int c = 0; c < FEAT; ++c)
                acc += __ldg(&w_head[o * FEAT + c]) * __ldg(&w_enc[c * 27 + k]);
            sw[t] = acc;
        } else {
            const int o = t - GD * 27;
            float acc = __ldg(&b_head[o]);
            #pragma unroll 8
            for (int c = 0; c < FEAT; ++c)
                acc += __ldg(&w_head[o * FEAT + c]) * __ldg(&b_enc[c]);
            sb[o] = acc;
        }
    }
    __syncthreads();

    const int p = blockIdx.x * 64 + tid;   // [0, HW)
    const int w = p % Ww;
    const int h = p / Ww;

    float pred[GD];
    #pragma unroll
    for (int o = 0; o < GD; ++o) pred[o] = sb[o];

    // Effective 3x3x3 conv, SAME zero padding (8 independent accumulators = ILP8).
    #pragma unroll
    for (int ci = 0; ci < CIN; ++ci) {
        #pragma unroll
        for (int ky = 0; ky < 3; ++ky) {
            const int y = h + ky - 1;
            #pragma unroll
            for (int kx = 0; kx < 3; ++kx) {
                const int x = w + kx - 1;
                float v = 0.f;
                if (y >= 0 && y < Hh && x >= 0 && x < Ww)
                    v = __ldg(&inp[ci * HW + y * Ww + x]);
                const int k = ci * 9 + ky * 3 + kx;
                #pragma unroll
                for (int o = 0; o < GD; ++o)
                    pred[o] += v * sw[o * 27 + k];
            }
        }
    }

    const float theta = (1.f / (1.f + expf(-pred[3]))) * 6.283185307179586f;
    const float s0 = (1.f / (1.f + expf(-pred[4]))) * 0.5f + 1e-6f;
    const float s1 = (1.f / (1.f + expf(-pred[5]))) * 0.5f + 1e-6f;
    const float off0 = tanhf(pred[6]);
    const float off1 = tanhf(pred[7]);

    const float c = cosf(theta), s = sinf(theta);
    const float v0 = s0 * s0, v1 = s1 * s1;
    const float S00 = c * c * v0 + s * s * v1;
    const float S01 = c * s * (v0 - v1);
    const float S11 = s * s * v0 + c * c * v1;
    const float det = S00 * S11 - S01 * S01;
    const float inv_det = 1.f / det;
    const float bmid = 0.5f * (S00 + S11);
    const float lam1 = bmid + sqrtf(fmaxf(0.1f, bmid * bmid - det));
    const float radius = ceilf(3.0f * sqrtf(lam1));

    const float coord0 = 2.0f * (float)w / (float)Ww - 1.0f;
    const float coord1 = 2.0f * (float)h / (float)Hh - 1.0f;
    const float x_ndc = coord0 + 2.0f * off0 / (float)Ww - 1.0f / (float)Ww;
    const float y_ndc = coord1 + 2.0f * off1 / (float)Hh - 1.0f / (float)Hh;
    const float cx = 0.5f * (float)Ww * (x_ndc + 1.0f) - 0.5f;
    const float cy = 0.5f * (float)Hh * (y_ndc + 1.0f) - 0.5f;

    int tmin_x = min(max((int)((cx - radius) / 16.0f), 0), TWt);
    int tmax_x = min(max((int)((cx + radius) / 16.0f) + 1, 0), TWt);
    int tmin_y = min(max((int)((cy - radius) / 16.0f), 0), THt);
    int tmax_y = min(max((int)((cy + radius) / 16.0f) + 1, 0), THt);
    if (!(radius > 0.0f)) { tmax_x = tmin_x; tmax_y = tmin_y; }

    GParam g;
    g.cx = cx; g.cy = cy;
    g.ca =  S11 * inv_det;
    g.cb = -S01 * inv_det;
    g.cc =  S00 * inv_det;
    g.r0 = pred[0]; g.r1 = pred[1]; g.r2 = pred[2];
    g.tminx = tmin_x; g.tmaxx = tmax_x; g.tminy = tmin_y; g.tmaxy = tmax_y;
    g_gauss[p] = g;
}

// ---------------------------------------------------------------------------
// Kernel 2: rasterize. 4 threads per pixel (144 blocks x 256 threads), each
// thread evaluates ~12 of the 49 candidate gaussians in the provably-
// sufficient 7x7 window, then a shfl butterfly reduces the 3 accumulators.
// Membership is decided purely on sigma in [0, ln255] — exactly the
// reference's alpha>=1/255 gate in real arithmetic.
// ---------------------------------------------------------------------------
__global__ __launch_bounds__(256)
void raster_kernel(float* __restrict__ out)
{
    const int gt  = blockIdx.x * 256 + threadIdx.x;   // [0, 4*HW)
    const int p   = gt >> 2;                          // pixel
    const int sub = gt & 3;                           // 0..3 within pixel
    const int px = p % Ww;
    const int py = p / Ww;
    const int tx = px >> 4;
    const int ty = py >> 4;
    const float fpx = (float)px;
    const float fpy = (float)py;

    float a0 = 0.f, a1 = 0.f, a2 = 0.f;

    // j = dgh*7 + dgw over the 7x7 window [p-2, p+4]^2, strided by 4 lanes.
    for (int j = sub; j < 49; j += 4) {
        const int gh = py - 2 + j / 7;
        const int gw = px - 2 + j % 7;
        if ((unsigned)gh >= Hh || (unsigned)gw >= Ww) continue;
        const GParam g = g_gauss[gh * Ww + gw];
        const float dx = g.cx - fpx;
        const float dy = g.cy - fpy;
        const float sigma = 0.5f * (g.ca * dx * dx + g.cc * dy * dy) + g.cb * dx * dy;
        if (!(sigma >= 0.f) || sigma > LN255) continue;
        if (tx < g.tminx || tx >= g.tmaxx || ty < g.tminy || ty >= g.tmaxy) continue;
        const float alpha = fminf(0.999f, __expf(-sigma));
        a0 += alpha * g.r0;
        a1 += alpha * g.r1;
        a2 += alpha * g.r2;
    }

    // Butterfly-reduce across the 4 lanes of this pixel.
    a0 += __shfl_xor_sync(0xFFFFFFFFu, a0, 1);
    a1 += __shfl_xor_sync(0xFFFFFFFFu, a1, 1);
    a2 += __shfl_xor_sync(0xFFFFFFFFu, a2, 1);
    a0 += __shfl_xor_sync(0xFFFFFFFFu, a0, 2);
    a1 += __shfl_xor_sync(0xFFFFFFFFu, a1, 2);
    a2 += __shfl_xor_sync(0xFFFFFFFFu, a2, 2);

    // Lanes 0/1/2 of each pixel group write channels 0/1/2.
    if (sub == 0)      out[0 * HW + p] = fminf(fmaxf(a0, 0.f), 1.f);
    else if (sub == 1) out[1 * HW + p] = fminf(fmaxf(a1, 0.f), 1.f);
    else if (sub == 2) out[2 * HW + p] = fminf(fmaxf(a2, 0.f), 1.f);
}

// ---------------------------------------------------------------------------
extern "C" void kernel_launch(void* const* d_in, const int* in_sizes, int n_in,
                              void* d_out, int out_size)
{
    const float* inp    = (const float*)d_in[0];
    const float* w_enc  = (const float*)d_in[1];
    const float* b_enc  = (const float*)d_in[2];
    const float* w_head = (const float*)d_in[3];
    const float* b_head = (const float*)d_in[4];
    float* out = (float*)d_out;

    gauss_params_kernel<<<144, 64>>>(inp, w_enc, b_enc, w_head, b_head);
    raster_kernel<<<144, 256>>>(out);
}

// round 7
// speedup vs baseline: 1.8436x; 1.2197x over previous
#include <cuda_runtime.h>
#include <math.h>

// Problem constants (B=1, C_IN=3, H=W=96, FEAT=64, GDIM=8, BLOCK=16)
#define Hh   96
#define Ww   96
#define HW   (96 * 96)
#define GD   8
#define FEAT 64
#define CIN  3
#define TWt  6
#define THt  6

#define LN255 5.5412635f   // ln(255); alpha >= 1/255  <=>  sigma <= ln(255)

// 32-byte gaussian record (tile bounds proven redundant: radius >= 2 always,
// and any candidate passing the sigma gate has |d| <= 1.665 < radius, which
// implies its tile interval contains the pixel's tile).
struct __align__(16) GParam {
    float cx, cy, ca, cb, cc, r0, r1, r2;
};

__device__ GParam g_gauss[HW];       // 288 KB scratch
__device__ float  g_sw[GD * 27];     // collapsed conv+head weights
__device__ float  g_sb[GD];          // collapsed bias

// ---------------------------------------------------------------------------
// Kernel 0: collapse conv+head into an effective 8x3x3x3 conv. One thread per
// weight entry; 64-MAC dot product each. Tiny (runs once per launch).
// ---------------------------------------------------------------------------
__global__ __launch_bounds__(256)
void collapse_kernel(const float* __restrict__ w_enc,
                     const float* __restrict__ b_enc,
                     const float* __restrict__ w_head,
                     const float* __restrict__ b_head)
{
    const int t = threadIdx.x;
    if (t < GD * 27) {
        const int o = t / 27, k = t % 27;
        float acc = 0.f;
        #pragma unroll 8
        for (int c = 0; c < FEAT; ++c)
            acc += __ldg(&w_head[o * FEAT + c]) * __ldg(&w_enc[c * 27 + k]);
        g_sw[t] = acc;
    } else if (t < GD * 27 + GD) {
        const int o = t - GD * 27;
        float acc = __ldg(&b_head[o]);
        #pragma unroll 8
        for (int c = 0; c < FEAT; ++c)
            acc += __ldg(&w_head[o * FEAT + c]) * __ldg(&b_enc[c]);
        g_sb[o] = acc;
    }
}

// ---------------------------------------------------------------------------
// Kernel 1: per-gaussian parameters. 144 blocks x 64 threads = 9216 gaussians.
// Weights are only COPIED to shared (no math), then each thread runs the
// effective 3x3x3 conv (ILP-8) and the activation/covariance chain.
// ---------------------------------------------------------------------------
__global__ __launch_bounds__(64)
void gauss_params_kernel(const float* __restrict__ inp)
{
    __shared__ float sw[GD * 27];
    __shared__ float sb[GD];

    const int tid = threadIdx.x;
    for (int t = tid; t < GD * 27; t += 64) sw[t] = g_sw[t];
    if (tid < GD) sb[tid] = g_sb[tid];
    __syncthreads();

    const int p = blockIdx.x * 64 + tid;   // [0, HW)
    const int w = p % Ww;
    const int h = p / Ww;

    float pred[GD];
    #pragma unroll
    for (int o = 0; o < GD; ++o) pred[o] = sb[o];

    // Effective 3x3x3 conv, SAME zero padding (8 independent accumulators).
    #pragma unroll
    for (int ci = 0; ci < CIN; ++ci) {
        #pragma unroll
        for (int ky = 0; ky < 3; ++ky) {
            const int y = h + ky - 1;
            #pragma unroll
            for (int kx = 0; kx < 3; ++kx) {
                const int x = w + kx - 1;
                float v = 0.f;
                if (y >= 0 && y < Hh && x >= 0 && x < Ww)
                    v = __ldg(&inp[ci * HW + y * Ww + x]);
                const int k = ci * 9 + ky * 3 + kx;
                #pragma unroll
                for (int o = 0; o < GD; ++o)
                    pred[o] += v * sw[o * 27 + k];
            }
        }
    }

    // Activations: fast-math sigmoids/rotation (<=1e-6 rel); tanh kept accurate
    // because center-position error is amplified by 1/lambda_min in sigma.
    const float theta = (1.f / (1.f + __expf(-pred[3]))) * 6.283185307179586f;
    const float s0 = (1.f / (1.f + __expf(-pred[4]))) * 0.5f + 1e-6f;
    const float s1 = (1.f / (1.f + __expf(-pred[5]))) * 0.5f + 1e-6f;
    const float off0 = tanhf(pred[6]);
    const float off1 = tanhf(pred[7]);

    const float c = __cosf(theta), s = __sinf(theta);
    const float v0 = s0 * s0, v1 = s1 * s1;
    const float S00 = c * c * v0 + s * s * v1;
    const float S01 = c * s * (v0 - v1);
    const float S11 = s * s * v0 + c * c * v1;
    const float det = S00 * S11 - S01 * S01;
    const float inv_det = 1.f / det;

    // NDC -> pixel center (coord0 varies with w, coord1 with h).
    const float coord0 = 2.0f * (float)w / (float)Ww - 1.0f;
    const float coord1 = 2.0f * (float)h / (float)Hh - 1.0f;
    const float x_ndc = coord0 + 2.0f * off0 / (float)Ww - 1.0f / (float)Ww;
    const float y_ndc = coord1 + 2.0f * off1 / (float)Hh - 1.0f / (float)Hh;

    GParam g;
    g.cx = 0.5f * (float)Ww * (x_ndc + 1.0f) - 0.5f;
    g.cy = 0.5f * (float)Hh * (y_ndc + 1.0f) - 0.5f;
    g.ca =  S11 * inv_det;
    g.cb = -S01 * inv_det;
    g.cc =  S00 * inv_det;
    g.r0 = pred[0]; g.r1 = pred[1]; g.r2 = pred[2];
    g_gauss[p] = g;
}

// ---------------------------------------------------------------------------
// Kernel 2: rasterize. 8 threads per pixel (144 blocks x 512 threads, single
// wave), each evaluating ~6 of the 49 candidates in the provably-sufficient
// 7x7 window; 3-step shfl butterfly reduces the 3 channel accumulators.
// Membership decided purely on sigma in [0, ln255] (== alpha>=1/255 gate);
// tile-bounds check proven redundant and removed.
// ---------------------------------------------------------------------------
__global__ __launch_bounds__(512)
void raster_kernel(float* __restrict__ out)
{
    const int gt  = blockIdx.x * 512 + threadIdx.x;   // [0, 8*HW)
    const int p   = gt >> 3;                          // pixel
    const int sub = gt & 7;                           // 0..7 within pixel
    const int px = p % Ww;
    const int py = p / Ww;
    const float fpx = (float)px;
    const float fpy = (float)py;

    float a0 = 0.f, a1 = 0.f, a2 = 0.f;

    // j = dgh*7 + dgw over the 7x7 window [p-2, p+4]^2, strided by 8 lanes.
    #pragma unroll
    for (int j = sub; j < 49; j += 8) {
        const int gh = py - 2 + j / 7;
        const int gw = px - 2 + j % 7;
        if ((unsigned)gh >= Hh || (unsigned)gw >= Ww) continue;
        const float4* q = reinterpret_cast<const float4*>(&g_gauss[gh * Ww + gw]);
        const float4 q0 = q[0];     // cx, cy, ca, cb
        const float4 q1 = q[1];     // cc, r0, r1, r2
        const float dx = q0.x - fpx;
        const float dy = q0.y - fpy;
        const float sigma = 0.5f * (q0.z * dx * dx + q1.x * dy * dy) + q0.w * dx * dy;
        if (!(sigma >= 0.f) || sigma > LN255) continue;
        const float alpha = fminf(0.999f, __expf(-sigma));
        a0 += alpha * q1.y;
        a1 += alpha * q1.z;
        a2 += alpha * q1.w;
    }

    // Butterfly-reduce across the 8 lanes of this pixel.
    #pragma unroll
    for (int m = 1; m < 8; m <<= 1) {
        a0 += __shfl_xor_sync(0xFFFFFFFFu, a0, m);
        a1 += __shfl_xor_sync(0xFFFFFFFFu, a1, m);
        a2 += __shfl_xor_sync(0xFFFFFFFFu, a2, m);
    }

    // Lanes 0/1/2 of each pixel group write channels 0/1/2.
    if (sub == 0)      out[0 * HW + p] = fminf(fmaxf(a0, 0.f), 1.f);
    else if (sub == 1) out[1 * HW + p] = fminf(fmaxf(a1, 0.f), 1.f);
    else if (sub == 2) out[2 * HW + p] = fminf(fmaxf(a2, 0.f), 1.f);
}

// ---------------------------------------------------------------------------
extern "C" void kernel_launch(void* const* d_in, const int* in_sizes, int n_in,
                              void* d_out, int out_size)
{
    const float* inp    = (const float*)d_in[0];
    const float* w_enc  = (const float*)d_in[1];
    const float* b_enc  = (const float*)d_in[2];
    const float* w_head = (const float*)d_in[3];
    const float* b_head = (const float*)d_in[4];
    float* out = (float*)d_out;

    collapse_kernel<<<1, 256>>>(w_enc, b_enc, w_head, b_head);
    gauss_params_kernel<<<144, 64>>>(inp);
    raster_kernel<<<144, 512>>>(out);
}

// round 8
// speedup vs baseline: 2.1336x; 1.1573x over previous
#include <cuda_runtime.h>
#include <math.h>

// Problem constants (B=1, C_IN=3, H=W=96, FEAT=64, GDIM=8, BLOCK=16)
#define Hh   96
#define Ww   96
#define HW   (96 * 96)
#define GD   8
#define FEAT 64
#define CIN  3

#define LN255 5.5412635f   // ln(255); alpha >= 1/255  <=>  sigma <= ln(255)

// 32-byte gaussian record (tile bounds proven redundant: radius >= 2 always,
// and any candidate passing the sigma gate has |d| <= 1.665 < radius, which
// implies its tile interval contains the pixel's tile).
struct __align__(16) GParam {
    float cx, cy, ca, cb, cc, r0, r1, r2;
};

__device__ GParam g_gauss[HW];       // 288 KB scratch
__device__ float  g_sw[GD * 27];     // collapsed conv+head weights
__device__ float  g_sb[GD];          // collapsed bias

// ---------------------------------------------------------------------------
// Kernel 0: collapse conv+head into an effective 8x3x3x3 conv.
// ONE WARP PER OUTPUT ENTRY (216 weights + 8 biases = 224 warps, 28 blocks).
// Each lane does 2 MACs; 5-step shfl butterfly reduces. All 7168 cold loads
// are issued concurrently across 28 SMs -> latency ~ one DRAM round trip,
// instead of the previous single-block 64-deep serial chain.
// ---------------------------------------------------------------------------
__global__ __launch_bounds__(256)
void collapse_kernel(const float* __restrict__ w_enc,
                     const float* __restrict__ b_enc,
                     const float* __restrict__ w_head,
                     const float* __restrict__ b_head)
{
    const int wid  = (blockIdx.x * 256 + threadIdx.x) >> 5;   // [0, 224)
    const int lane = threadIdx.x & 31;

    float acc;
    if (wid < GD * 27) {
        const int o = wid / 27, k = wid % 27;
        const float wh0 = __ldg(&w_head[o * FEAT + lane]);
        const float wh1 = __ldg(&w_head[o * FEAT + 32 + lane]);
        const float we0 = __ldg(&w_enc[lane * 27 + k]);
        const float we1 = __ldg(&w_enc[(32 + lane) * 27 + k]);
        acc = wh0 * we0 + wh1 * we1;
    } else {
        const int o = wid - GD * 27;   // [0, 8)
        const float wh0 = __ldg(&w_head[o * FEAT + lane]);
        const float wh1 = __ldg(&w_head[o * FEAT + 32 + lane]);
        const float be0 = __ldg(&b_enc[lane]);
        const float be1 = __ldg(&b_enc[32 + lane]);
        acc = wh0 * be0 + wh1 * be1;
    }

    #pragma unroll
    for (int m = 16; m >= 1; m >>= 1)
        acc += __shfl_xor_sync(0xFFFFFFFFu, acc, m);

    if (lane == 0) {
        if (wid < GD * 27) g_sw[wid] = acc;
        else               g_sb[wid - GD * 27] = acc + __ldg(&b_head[wid - GD * 27]);
    }
}

// ---------------------------------------------------------------------------
// Kernel 1: per-gaussian parameters. 144 blocks x 64 threads = 9216 gaussians.
// Weights are only COPIED to shared (no math), then each thread runs the
// effective 3x3x3 conv (ILP-8) and the activation/covariance chain.
// ---------------------------------------------------------------------------
__global__ __launch_bounds__(64)
void gauss_params_kernel(const float* __restrict__ inp)
{
    __shared__ float sw[GD * 27];
    __shared__ float sb[GD];

    const int tid = threadIdx.x;
    for (int t = tid; t < GD * 27; t += 64) sw[t] = g_sw[t];
    if (tid < GD) sb[tid] = g_sb[tid];
    __syncthreads();

    const int p = blockIdx.x * 64 + tid;   // [0, HW)
    const int w = p % Ww;
    const int h = p / Ww;

    float pred[GD];
    #pragma unroll
    for (int o = 0; o < GD; ++o) pred[o] = sb[o];

    // Effective 3x3x3 conv, SAME zero padding (8 independent accumulators).
    #pragma unroll
    for (int ci = 0; ci < CIN; ++ci) {
        #pragma unroll
        for (int ky = 0; ky < 3; ++ky) {
            const int y = h + ky - 1;
            #pragma unroll
            for (int kx = 0; kx < 3; ++kx) {
                const int x = w + kx - 1;
                float v = 0.f;
                if (y >= 0 && y < Hh && x >= 0 && x < Ww)
                    v = __ldg(&inp[ci * HW + y * Ww + x]);
                const int k = ci * 9 + ky * 3 + kx;
                #pragma unroll
                for (int o = 0; o < GD; ++o)
                    pred[o] += v * sw[o * 27 + k];
            }
        }
    }

    // Activations: fast-math sigmoids/rotation (<=1e-6 rel); tanh kept accurate
    // because center-position error is amplified by 1/lambda_min in sigma.
    const float theta = (1.f / (1.f + __expf(-pred[3]))) * 6.283185307179586f;
    const float s0 = (1.f / (1.f + __expf(-pred[4]))) * 0.5f + 1e-6f;
    const float s1 = (1.f / (1.f + __expf(-pred[5]))) * 0.5f + 1e-6f;
    const float off0 = tanhf(pred[6]);
    const float off1 = tanhf(pred[7]);

    const float c = __cosf(theta), s = __sinf(theta);
    const float v0 = s0 * s0, v1 = s1 * s1;
    const float S00 = c * c * v0 + s * s * v1;
    const float S01 = c * s * (v0 - v1);
    const float S11 = s * s * v0 + c * c * v1;
    const float det = S00 * S11 - S01 * S01;
    const float inv_det = 1.f / det;

    // NDC -> pixel center (coord0 varies with w, coord1 with h).
    const float coord0 = 2.0f * (float)w / (float)Ww - 1.0f;
    const float coord1 = 2.0f * (float)h / (float)Hh - 1.0f;
    const float x_ndc = coord0 + 2.0f * off0 / (float)Ww - 1.0f / (float)Ww;
    const float y_ndc = coord1 + 2.0f * off1 / (float)Hh - 1.0f / (float)Hh;

    GParam g;
    g.cx = 0.5f * (float)Ww * (x_ndc + 1.0f) - 0.5f;
    g.cy = 0.5f * (float)Hh * (y_ndc + 1.0f) - 0.5f;
    g.ca =  S11 * inv_det;
    g.cb = -S01 * inv_det;
    g.cc =  S00 * inv_det;
    g.r0 = pred[0]; g.r1 = pred[1]; g.r2 = pred[2];
    g_gauss[p] = g;
}

// ---------------------------------------------------------------------------
// Kernel 2: rasterize. 8 threads per pixel (144 blocks x 512 threads, single
// wave), each evaluating ~6 of the 49 candidates in the provably-sufficient
// 7x7 window; 3-step shfl butterfly reduces the 3 channel accumulators.
// Membership decided purely on sigma in [0, ln255] (== alpha>=1/255 gate);
// tile-bounds check proven redundant and removed.
// ---------------------------------------------------------------------------
__global__ __launch_bounds__(512)
void raster_kernel(float* __restrict__ out)
{
    const int gt  = blockIdx.x * 512 + threadIdx.x;   // [0, 8*HW)
    const int p   = gt >> 3;                          // pixel
    const int sub = gt & 7;                           // 0..7 within pixel
    const int px = p % Ww;
    const int py = p / Ww;
    const float fpx = (float)px;
    const float fpy = (float)py;

    float a0 = 0.f, a1 = 0.f, a2 = 0.f;

    // j = dgh*7 + dgw over the 7x7 window [p-2, p+4]^2, strided by 8 lanes.
    #pragma unroll
    for (int j = sub; j < 49; j += 8) {
        const int gh = py - 2 + j / 7;
        const int gw = px - 2 + j % 7;
        if ((unsigned)gh >= Hh || (unsigned)gw >= Ww) continue;
        const float4* q = reinterpret_cast<const float4*>(&g_gauss[gh * Ww + gw]);
        const float4 q0 = q[0];     // cx, cy, ca, cb
        const float4 q1 = q[1];     // cc, r0, r1, r2
        const float dx = q0.x - fpx;
        const float dy = q0.y - fpy;
        const float sigma = 0.5f * (q0.z * dx * dx + q1.x * dy * dy) + q0.w * dx * dy;
        if (!(sigma >= 0.f) || sigma > LN255) continue;
        const float alpha = fminf(0.999f, __expf(-sigma));
        a0 += alpha * q1.y;
        a1 += alpha * q1.z;
        a2 += alpha * q1.w;
    }

    // Butterfly-reduce across the 8 lanes of this pixel.
    #pragma unroll
    for (int m = 1; m < 8; m <<= 1) {
        a0 += __shfl_xor_sync(0xFFFFFFFFu, a0, m);
        a1 += __shfl_xor_sync(0xFFFFFFFFu, a1, m);
        a2 += __shfl_xor_sync(0xFFFFFFFFu, a2, m);
    }

    // Lanes 0/1/2 of each pixel group write channels 0/1/2.
    if (sub == 0)      out[0 * HW + p] = fminf(fmaxf(a0, 0.f), 1.f);
    else if (sub == 1) out[1 * HW + p] = fminf(fmaxf(a1, 0.f), 1.f);
    else if (sub == 2) out[2 * HW + p] = fminf(fmaxf(a2, 0.f), 1.f);
}

// ---------------------------------------------------------------------------
extern "C" void kernel_launch(void* const* d_in, const int* in_sizes, int n_in,
                              void* d_out, int out_size)
{
    const float* inp    = (const float*)d_in[0];
    const float* w_enc  = (const float*)d_in[1];
    const float* b_enc  = (const float*)d_in[2];
    const float* w_head = (const float*)d_in[3];
    const float* b_head = (const float*)d_in[4];
    float* out = (float*)d_out;

    collapse_kernel<<<28, 256>>>(w_enc, b_enc, w_head, b_head);
    gauss_params_kernel<<<144, 64>>>(inp);
    raster_kernel<<<144, 512>>>(out);
}

// round 9
// speedup vs baseline: 2.3798x; 1.1154x over previous
#include <cuda_runtime.h>
#include <math.h>

// Problem constants (B=1, C_IN=3, H=W=96, FEAT=64, GDIM=8, BLOCK=16)
#define Hh   96
#define Ww   96
#define HW   (96 * 96)
#define GD   8
#define FEAT 64
#define CIN  3

#define NB   144   // blocks: <=148 SMs, 1 block/SM -> all co-resident in wave 1
#define NT   512   // threads/block: 64 gaussians x 8 outputs; 64 pixels x 8 lanes

#define LN255 5.5412635f   // ln(255); alpha >= 1/255  <=>  sigma <= ln(255)

// 32-byte gaussian record (tile bounds proven redundant: radius >= 2 always,
// and any sigma-gate survivor has |d| <= 1.665 < radius => tile test passes).
struct __align__(16) GParam {
    float cx, cy, ca, cb, cc, r0, r1, r2;
};

__device__ GParam g_gauss[HW];   // 288 KB scratch (device global: no allocations)
__device__ int    g_arrive = 0;  // grid barrier counters (self-resetting per launch)
__device__ int    g_depart = 0;

// ---------------------------------------------------------------------------
// Single fused kernel: stage weights -> collapse conv+head -> per-gaussian
// params -> device-wide barrier -> rasterize. One launch, one cold-DRAM trip.
// ---------------------------------------------------------------------------
__global__ __launch_bounds__(NT)
void fused_kernel(const float* __restrict__ inp,
                  const float* __restrict__ w_enc,
                  const float* __restrict__ b_enc,
                  const float* __restrict__ w_head,
                  const float* __restrict__ b_head,
                  float* __restrict__ out)
{
    __shared__ float s_we[FEAT * 27];   // w_enc  [c*27 + k]
    __shared__ float s_wh[FEAT * GD];   // w_head TRANSPOSED [c*8 + o] (bank-friendly)
    __shared__ float s_be[FEAT];
    __shared__ float s_bh[GD];
    __shared__ float sw[GD * 27];       // collapsed weights [o*27 + k]
    __shared__ float sb[GD];
    __shared__ float spred[64 * GD];    // per-gaussian raw preds [gi*8 + o]

    const int tid = threadIdx.x;
    const int bid = blockIdx.x;

    // ---- stage raw weights to shared (one coalesced cold-DRAM trip) --------
    for (int t = tid; t < FEAT * 27; t += NT) s_we[t] = __ldg(&w_enc[t]);
    {   // transpose w_head into [c][o]
        const int c = tid >> 3, o = tid & 7;           // tid < 512 == FEAT*GD
        s_wh[c * GD + o] = __ldg(&w_head[o * FEAT + c]);
    }
    if (tid < FEAT) s_be[tid] = __ldg(&b_enc[tid]);
    if (tid < GD)   s_bh[tid] = __ldg(&b_head[tid]);
    __syncthreads();

    // ---- collapse: w_eff[o,k] = sum_c w_head[o,c] * w_enc[c,k] -------------
    if (tid < GD * 27) {
        const int o = tid / 27, k = tid % 27;
        float a0 = 0.f, a1 = 0.f, a2 = 0.f, a3 = 0.f;
        #pragma unroll
        for (int c = 0; c < FEAT; c += 4) {
            a0 += s_wh[(c    ) * GD + o] * s_we[(c    ) * 27 + k];
            a1 += s_wh[(c + 1) * GD + o] * s_we[(c + 1) * 27 + k];
            a2 += s_wh[(c + 2) * GD + o] * s_we[(c + 2) * 27 + k];
            a3 += s_wh[(c + 3) * GD + o] * s_we[(c + 3) * 27 + k];
        }
        sw[tid] = (a0 + a1) + (a2 + a3);
    } else if (tid < GD * 27 + GD) {
        const int o = tid - GD * 27;
        float acc = s_bh[o];
        #pragma unroll
        for (int c = 0; c < FEAT; ++c)
            acc += s_wh[c * GD + o] * s_be[c];
        sb[o] = acc;
    }
    __syncthreads();

    // ---- phase A1: conv, 8 threads per gaussian (27 MACs each) -------------
    {
        const int gi = tid >> 3;          // gaussian within block [0,64)
        const int o  = tid & 7;           // output channel
        const int p  = bid * 64 + gi;     // [0, HW)
        const int w  = p % Ww;
        const int h  = p / Ww;

        float acc = sb[o];
        #pragma unroll
        for (int ci = 0; ci < CIN; ++ci) {
            #pragma unroll
            for (int ky = 0; ky < 3; ++ky) {
                const int y = h + ky - 1;
                #pragma unroll
                for (int kx = 0; kx < 3; ++kx) {
                    const int x = w + kx - 1;
                    float v = 0.f;
                    if (y >= 0 && y < Hh && x >= 0 && x < Ww)
                        v = __ldg(&inp[ci * HW + y * Ww + x]);
                    acc += v * sw[o * 27 + ci * 9 + ky * 3 + kx];
                }
            }
        }
        spred[gi * GD + o] = acc;
    }
    __syncthreads();

    // ---- phase A2: activation/covariance chain, 1 thread per gaussian ------
    if (tid < 64) {
        const int p = bid * 64 + tid;
        const int w = p % Ww;
        const int h = p / Ww;
        float pred[GD];
        #pragma unroll
        for (int o = 0; o < GD; ++o) pred[o] = spred[tid * GD + o];

        const float theta = (1.f / (1.f + __expf(-pred[3]))) * 6.283185307179586f;
        const float s0 = (1.f / (1.f + __expf(-pred[4]))) * 0.5f + 1e-6f;
        const float s1 = (1.f / (1.f + __expf(-pred[5]))) * 0.5f + 1e-6f;
        const float off0 = tanhf(pred[6]);
        const float off1 = tanhf(pred[7]);

        const float c = __cosf(theta), s = __sinf(theta);
        const float v0 = s0 * s0, v1 = s1 * s1;
        const float S00 = c * c * v0 + s * s * v1;
        const float S01 = c * s * (v0 - v1);
        const float S11 = s * s * v0 + c * c * v1;
        const float det = S00 * S11 - S01 * S01;
        const float inv_det = 1.f / det;

        const float coord0 = 2.0f * (float)w / (float)Ww - 1.0f;
        const float coord1 = 2.0f * (float)h / (float)Hh - 1.0f;
        const float x_ndc = coord0 + 2.0f * off0 / (float)Ww - 1.0f / (float)Ww;
        const float y_ndc = coord1 + 2.0f * off1 / (float)Hh - 1.0f / (float)Hh;

        GParam g;
        g.cx = 0.5f * (float)Ww * (x_ndc + 1.0f) - 0.5f;
        g.cy = 0.5f * (float)Hh * (y_ndc + 1.0f) - 0.5f;
        g.ca =  S11 * inv_det;
        g.cb = -S01 * inv_det;
        g.cc =  S00 * inv_det;
        g.r0 = pred[0]; g.r1 = pred[1]; g.r2 = pred[2];
        g_gauss[p] = g;
    }

    // ---- device-wide barrier (all NB blocks resident in wave 1) ------------
    __threadfence();                     // publish g_gauss GPU-wide
    __syncthreads();                     // whole block done writing
    if (tid == 0) {
        atomicAdd(&g_arrive, 1);
        while (*(volatile int*)&g_arrive < NB) { }
        __threadfence();
        atomicAdd(&g_depart, 1);         // "I will never read g_arrive again"
    }
    __syncthreads();                     // released; all g_gauss visible (L1 cold)

    // ---- phase B: rasterize, 8 lanes per pixel -----------------------------
    {
        const int gt  = bid * NT + tid;  // [0, 8*HW)
        const int p   = gt >> 3;
        const int sub = gt & 7;
        const int px = p % Ww;
        const int py = p / Ww;
        const float fpx = (float)px;
        const float fpy = (float)py;

        float a0 = 0.f, a1 = 0.f, a2 = 0.f;

        #pragma unroll
        for (int j = sub; j < 49; j += 8) {
            const int gh = py - 2 + j / 7;
            const int gw = px - 2 + j % 7;
            if ((unsigned)gh >= Hh || (unsigned)gw >= Ww) continue;
            const float4* q = reinterpret_cast<const float4*>(&g_gauss[gh * Ww + gw]);
            const float4 q0 = q[0];      // cx, cy, ca, cb
            const float4 q1 = q[1];      // cc, r0, r1, r2
            const float dx = q0.x - fpx;
            const float dy = q0.y - fpy;
            const float sigma = 0.5f * (q0.z * dx * dx + q1.x * dy * dy) + q0.w * dx * dy;
            if (!(sigma >= 0.f) || sigma > LN255) continue;
            const float alpha = fminf(0.999f, __expf(-sigma));
            a0 += alpha * q1.y;
            a1 += alpha * q1.z;
            a2 += alpha * q1.w;
        }

        #pragma unroll
        for (int m = 1; m < 8; m <<= 1) {
            a0 += __shfl_xor_sync(0xFFFFFFFFu, a0, m);
            a1 += __shfl_xor_sync(0xFFFFFFFFu, a1, m);
            a2 += __shfl_xor_sync(0xFFFFFFFFu, a2, m);
        }

        if (sub == 0)      out[0 * HW + p] = fminf(fmaxf(a0, 0.f), 1.f);
        else if (sub == 1) out[1 * HW + p] = fminf(fmaxf(a1, 0.f), 1.f);
        else if (sub == 2) out[2 * HW + p] = fminf(fmaxf(a2, 0.f), 1.f);
    }

    // ---- reset barrier counters for the next graph replay ------------------
    if (bid == 0 && tid == 0) {
        while (*(volatile int*)&g_depart < NB) { }   // nobody touches g_arrive anymore
        atomicExch(&g_arrive, 0);
        atomicExch(&g_depart, 0);
    }
}

// ---------------------------------------------------------------------------
extern "C" void kernel_launch(void* const* d_in, const int* in_sizes, int n_in,
                              void* d_out, int out_size)
{
    const float* inp    = (const float*)d_in[0];
    const float* w_enc  = (const float*)d_in[1];
    const float* b_enc  = (const float*)d_in[2];
    const float* w_head = (const float*)d_in[3];
    const float* b_head = (const float*)d_in[4];
    float* out = (float*)d_out;

    fused_kernel<<<NB, NT>>>(inp, w_enc, b_enc, w_head, b_head, out);
}